// round 11
// baseline (speedup 1.0000x reference)
#include <cuda_runtime.h>
#include <math.h>

// Problem constants (fixed by setup_inputs)
#define NB 16
#define NP 32768
#define NG 128
#define TK 4                      // top-k (expand_num)
#define CSPLIT 8                  // prior-chunks per image (streams per truth)
#define TPB 16                    // truths per block (2 per warp)
#define WPB 8                     // warps per block
#define NT1 (WPB * 32)            // 256 threads
#define NTGRP (NG / TPB)          // 8 truth-groups per image
#define CHUNK (NP / CSPLIT)       // 4096 priors per stream
#define TILE 2048                 // smem tile of priors
#define NTILES (CHUNK / TILE)     // 2
#define ITERS (TILE / 32)         // 64 warp-iters per tile
#define NBG (NB * NG)             // 2048 truths
#define NCPT (CSPLIT * TK)        // 32 candidates per truth

// Candidate buffer (512 KB) + last-block counters (zero-init, reset each launch).
__device__ float2 g_cand[NBG * NCPT];
__device__ int    g_cnt[NB * NTGRP];

// ── (q, idx) total order: value desc, index asc (jax.lax.top_k stable) ──────
__device__ __forceinline__ bool better(float av, int ai, float bv, int bi) {
    return (av > bv) || (av == bv && ai < bi);
}

// Uniform insert of ballot'd candidates into a warp-replicated top-4
// (inter, denom, idx) list ordered by exact cross-multiplication ratio.
#define INSERT_LIST(m, inter, denom, bidx,                                    \
                    Li0, Li1, Li2, Li3, Ld0, Ld1, Ld2, Ld3,                   \
                    Lx0, Lx1, Lx2, Lx3)                                       \
    while (m) {                                                               \
        int l = __ffs(m) - 1; m &= m - 1;                                     \
        float ci = __shfl_sync(0xffffffffu, inter, l);                        \
        float cd = __shfl_sync(0xffffffffu, denom, l);                        \
        int   cx = (bidx) + l;                                                \
        bool c3 = __fmul_rn(ci, Ld3) > __fmul_rn(Li3, cd);                    \
        if (c3) {                                                             \
            bool c2 = __fmul_rn(ci, Ld2) > __fmul_rn(Li2, cd);                \
            bool c1 = __fmul_rn(ci, Ld1) > __fmul_rn(Li1, cd);                \
            bool c0 = __fmul_rn(ci, Ld0) > __fmul_rn(Li0, cd);                \
            Li3 = c2 ? Li2 : ci;  Ld3 = c2 ? Ld2 : cd;  Lx3 = c2 ? Lx2 : cx;  \
            Li2 = c1 ? Li1 : (c2 ? ci : Li2);                                 \
            Ld2 = c1 ? Ld1 : (c2 ? cd : Ld2);                                 \
            Lx2 = c1 ? Lx1 : (c2 ? cx : Lx2);                                 \
            Li1 = c0 ? Li0 : (c1 ? ci : Li1);                                 \
            Ld1 = c0 ? Ld0 : (c1 ? cd : Ld1);                                 \
            Lx1 = c0 ? Lx0 : (c1 ? cx : Lx1);                                 \
            Li0 = c0 ? ci : Li0;                                              \
            Ld0 = c0 ? cd : Ld0;                                              \
            Lx0 = c0 ? cx : Lx0;                                              \
        }                                                                     \
    }

// ── Fused kernel: warp = 2 truths; last block per truth-group merges+encodes ─
__global__ __launch_bounds__(NT1)
void ptl_fused(const float* __restrict__ rois,
               const float* __restrict__ targets,
               float* __restrict__ out) {
    const int blk  = blockIdx.x;                   // NB * NTGRP * CSPLIT = 1024
    const int b    = blk / (NTGRP * CSPLIT);
    const int rem  = blk % (NTGRP * CSPLIT);
    const int tg   = rem / CSPLIT;
    const int cs   = rem % CSPLIT;
    const int tid  = threadIdx.x;
    const int lane = tid & 31;
    const int w    = tid >> 5;
    const int gA   = tg * TPB + 2 * w;             // warp's first truth
    const int gB   = gA + 1;                       // warp's second truth

    __shared__ float4 s_pri[TILE];                 // 32 KB
    __shared__ int    s_last;

    // Truth boxes (uniform per warp; L1-broadcast).
    float4 ta = __ldg(&((const float4*)targets)[(size_t)b * NG + gA]);
    float4 tb = __ldg(&((const float4*)targets)[(size_t)b * NG + gB]);
    const float ax1 = ta.x, ay1 = ta.y, ax2 = ta.z, ay2 = ta.w;
    const float bx1 = tb.x, by1 = tb.y, bx2 = tb.z, by2 = tb.w;
    const float aar = __fmul_rn(ax2 - ax1, ay2 - ay1);   // rounded once (jax)
    const float bar = __fmul_rn(bx2 - bx1, by2 - by1);

    // Two warp-replicated top-4 lists (inter, denom, idx); sentinel -1/1.
    float Ai0 = -1.0f, Ai1 = -1.0f, Ai2 = -1.0f, Ai3 = -1.0f;
    float Ad0 =  1.0f, Ad1 =  1.0f, Ad2 =  1.0f, Ad3 =  1.0f;
    int   Ax0 = 0x7fffffff, Ax1 = 0x7fffffff, Ax2 = 0x7fffffff, Ax3 = 0x7fffffff;
    float Bi0 = -1.0f, Bi1 = -1.0f, Bi2 = -1.0f, Bi3 = -1.0f;
    float Bd0 =  1.0f, Bd1 =  1.0f, Bd2 =  1.0f, Bd3 =  1.0f;
    int   Bx0 = 0x7fffffff, Bx1 = 0x7fffffff, Bx2 = 0x7fffffff, Bx3 = 0x7fffffff;

    const float4* pri = (const float4*)(rois + ((size_t)b * 2 + 1) * (size_t)NP * 4);

    for (int tile = 0; tile < NTILES; tile++) {
        const int base = cs * CHUNK + tile * TILE;

        // Cooperative stage: 256 threads x 8 float4.
#pragma unroll
        for (int k = tid; k < TILE; k += NT1)
            s_pri[k] = __ldg(&pri[base + k]);
        __syncthreads();

#pragma unroll 4
        for (int i = 0; i < ITERS; i++) {
            float4 pr = s_pri[i * 32 + lane];      // LDS.128, conflict-free
            float area_p = __fmul_rn(pr.z - pr.x, pr.w - pr.y);  // shared, jax bits

            // Truth A
            float lxA = fmaxf(ax1, pr.x);
            float lyA = fmaxf(ay1, pr.y);
            float rxA = fminf(ax2, pr.z);
            float ryA = fminf(ay2, pr.w);
            float wdA = fmaxf(rxA - lxA, 0.0f);
            float htA = fmaxf(ryA - lyA, 0.0f);
            float inA = __fmul_rn(wdA, htA);
            float deA = (aar + area_p) - inA;
            bool pA = __fmul_rn(inA, Ad3) > __fmul_rn(Ai3, deA);
            unsigned mA = __ballot_sync(0xffffffffu, pA);

            // Truth B
            float lxB = fmaxf(bx1, pr.x);
            float lyB = fmaxf(by1, pr.y);
            float rxB = fminf(bx2, pr.z);
            float ryB = fminf(by2, pr.w);
            float wdB = fmaxf(rxB - lxB, 0.0f);
            float htB = fmaxf(ryB - lyB, 0.0f);
            float inB = __fmul_rn(wdB, htB);
            float deB = (bar + area_p) - inB;
            bool pB = __fmul_rn(inB, Bd3) > __fmul_rn(Bi3, deB);
            unsigned mB = __ballot_sync(0xffffffffu, pB);

            INSERT_LIST(mA, inA, deA, base + i * 32,
                        Ai0, Ai1, Ai2, Ai3, Ad0, Ad1, Ad2, Ad3,
                        Ax0, Ax1, Ax2, Ax3)
            INSERT_LIST(mB, inB, deB, base + i * 32,
                        Bi0, Bi1, Bi2, Bi3, Bd0, Bd1, Bd2, Bd3,
                        Bx0, Bx1, Bx2, Bx3)
        }
        __syncthreads();
    }

    // Epilogue: lanes 0-3 finalize truth A's k=lane; lanes 4-7 truth B's.
    if (lane < 2 * TK) {
        bool isA = lane < TK;
        int  k   = lane & 3;
        float si = isA ? ((k == 0) ? Ai0 : (k == 1) ? Ai1 : (k == 2) ? Ai2 : Ai3)
                       : ((k == 0) ? Bi0 : (k == 1) ? Bi1 : (k == 2) ? Bi2 : Bi3);
        float sd = isA ? ((k == 0) ? Ad0 : (k == 1) ? Ad1 : (k == 2) ? Ad2 : Ad3)
                       : ((k == 0) ? Bd0 : (k == 1) ? Bd1 : (k == 2) ? Bd2 : Bd3);
        int   sx = isA ? ((k == 0) ? Ax0 : (k == 1) ? Ax1 : (k == 2) ? Ax2 : Ax3)
                       : ((k == 0) ? Bx0 : (k == 1) ? Bx1 : (k == 2) ? Bx2 : Bx3);
        float q = (sx == 0x7fffffff) ? -1e30f : __fdiv_rn(si, sd);  // jax bits
        int bg = b * NG + (isA ? gA : gB);
        g_cand[(size_t)bg * NCPT + cs * TK + k] = make_float2(q, __int_as_float(sx));
    }

    // ── Last-block merge + encode (replaces phase 2) ────────────────────────
    __threadfence();
    __syncthreads();
    if (tid == 0) {
        int old = atomicAdd(&g_cnt[b * NTGRP + tg], 1);
        s_last = (old == CSPLIT - 1) ? 1 : 0;
    }
    __syncthreads();
    if (s_last) {
        __threadfence();
        if (tid < TPB * TK) {                       // 64 threads: (truth, k)
            int lt = tid >> 2, k = tid & 3;
            int bg = b * NG + tg * TPB + lt;

            float v[TK]; int ix[TK];
#pragma unroll
            for (int j = 0; j < TK; j++) { v[j] = -1e30f; ix[j] = 0x7fffffff; }

            const float4* cand = (const float4*)(g_cand + (size_t)bg * NCPT);
#pragma unroll
            for (int c = 0; c < NCPT / 2; c++) {
                float4 cc = __ldcg(&cand[c]);       // L2 (skip L1; cross-SM data)
                float qs[2]  = {cc.x, cc.z};
                int   qis[2] = {__float_as_int(cc.y), __float_as_int(cc.w)};
#pragma unroll
                for (int t = 0; t < 2; t++) {
                    float q = qs[t]; int qi = qis[t];
                    if (better(q, qi, v[3], ix[3])) {
                        if (better(q, qi, v[2], ix[2])) {
                            v[3] = v[2]; ix[3] = ix[2];
                            if (better(q, qi, v[1], ix[1])) {
                                v[2] = v[1]; ix[2] = ix[1];
                                if (better(q, qi, v[0], ix[0])) {
                                    v[1] = v[0]; ix[1] = ix[0];
                                    v[0] = q; ix[0] = qi;
                                } else { v[1] = q; ix[1] = qi; }
                            } else { v[2] = q; ix[2] = qi; }
                        } else { v[3] = q; ix[3] = qi; }
                    }
                }
            }
            const int p = ix[k];

            // Encode one output row (identical rounding to reference).
            float gx1 = targets[(size_t)bg * 4 + 0];
            float gy1 = targets[(size_t)bg * 4 + 1];
            float gx2 = targets[(size_t)bg * 4 + 2];
            float gy2 = targets[(size_t)bg * 4 + 3];
            float gcx = (gx1 + gx2) * 0.5f;
            float gcy = (gy1 + gy2) * 0.5f;
            float gw  = gx2 - gx1;
            float gh  = gy2 - gy1;

            float4 pr = __ldg(&pri[p]);
            float pcx = (pr.x + pr.z) * 0.5f;
            float pcy = (pr.y + pr.w) * 0.5f;
            float pw  = pr.z - pr.x;
            float ph  = pr.w - pr.y;
            float4 o;
            o.x = (gcx - pcx) / (0.1f * pw);
            o.y = (gcy - pcy) / (0.1f * ph);
            o.z = logf(gw / pw) / 0.2f;
            o.w = logf(gh / ph) / 0.2f;
            ((float4*)out)[(size_t)bg * TK + k] = o;
        }
        if (tid == 0) g_cnt[b * NTGRP + tg] = 0;    // reset for next launch/replay
    }
}

extern "C" void kernel_launch(void* const* d_in, const int* in_sizes, int n_in,
                              void* d_out, int out_size) {
    const float* rois    = (const float*)d_in[0];   // (16, 2, 32768, 4) f32
    const float* targets = (const float*)d_in[1];   // (16, 128, 4) f32
    float* out           = (float*)d_out;           // (16, 512, 4) f32
    (void)in_sizes; (void)n_in; (void)out_size;

    ptl_fused<<<NB * NTGRP * CSPLIT, NT1>>>(rois, targets, out);
}

// round 12
// speedup vs baseline: 1.0506x; 1.0506x over previous
#include <cuda_runtime.h>
#include <math.h>

// Problem constants (fixed by setup_inputs)
#define NB 16
#define NP 32768
#define NG 128
#define TK 4                      // top-k (expand_num)
#define CSPLIT 4                  // prior-chunks per image (streams per truth)
#define WPB 16                    // warps (=truths) per block
#define NT1 (WPB * 32)            // 512 threads
#define TPB WPB                   // truths per block
#define NTGRP (NG / TPB)          // 8 truth-groups per image
#define CHUNK (NP / CSPLIT)       // 8192 priors per stream
#define TILE 2048                 // smem tile of priors
#define NTILES (CHUNK / TILE)     // 4
#define ITERS (TILE / 32)         // 64 warp-iters per tile
#define NBG (NB * NG)             // 2048 truths
#define NCPT (CSPLIT * TK)        // 16 candidates per truth

// Candidate buffer (256 KB) + last-block counters (zero-init, reset each launch).
__device__ float2 g_cand[NBG * NCPT];
__device__ int    g_cnt[NB * NTGRP];

// ── (q, idx) total order: value desc, index asc (jax.lax.top_k stable) ──────
__device__ __forceinline__ bool better(float av, int ai, float bv, int bi) {
    return (av > bv) || (av == bv && ai < bi);
}

// ── Fused kernel: warp = one truth; last block per (b,tg) merges + encodes ──
__global__ __launch_bounds__(NT1)
void ptl_fused(const float* __restrict__ rois,
               const float* __restrict__ targets,
               float* __restrict__ out) {
    const int blk  = blockIdx.x;                   // NB * NTGRP * CSPLIT = 512
    const int b    = blk / (NTGRP * CSPLIT);
    const int rem  = blk % (NTGRP * CSPLIT);
    const int tg   = rem / CSPLIT;
    const int cs   = rem % CSPLIT;
    const int tid  = threadIdx.x;
    const int lane = tid & 31;
    const int w    = tid >> 5;
    const int g    = tg * TPB + w;                 // this warp's truth

    __shared__ float4 s_pri[TILE];                 // 32 KB
    __shared__ int    s_last;

    // My warp's truth box (uniform across lanes; L1-broadcast).
    float4 tb = __ldg(&((const float4*)targets)[(size_t)b * NG + g]);
    const float tx1 = tb.x, ty1 = tb.y, tx2 = tb.z, ty2 = tb.w;
    const float tar = __fmul_rn(tx2 - tx1, ty2 - ty1);    // rounded once (jax)

    // Warp-replicated top-4 as (inter, denom, idx); sentinel ratio = -1/1.
    float Li0 = -1.0f, Li1 = -1.0f, Li2 = -1.0f, Li3 = -1.0f;
    float Ld0 =  1.0f, Ld1 =  1.0f, Ld2 =  1.0f, Ld3 =  1.0f;
    int   Lx0 = 0x7fffffff, Lx1 = 0x7fffffff, Lx2 = 0x7fffffff, Lx3 = 0x7fffffff;

    const float4* pri = (const float4*)(rois + ((size_t)b * 2 + 1) * (size_t)NP * 4);

    for (int tile = 0; tile < NTILES; tile++) {
        const int base = cs * CHUNK + tile * TILE;

        // Cooperative stage: 512 threads x 4 float4 each.
#pragma unroll
        for (int k = tid; k < TILE; k += NT1)
            s_pri[k] = __ldg(&pri[base + k]);
        __syncthreads();

#pragma unroll 4
        for (int i = 0; i < ITERS; i++) {
            float4 pr = s_pri[i * 32 + lane];            // LDS.128, conflict-free
            float area_p = __fmul_rn(pr.z - pr.x, pr.w - pr.y);  // regs, jax bits
            float lx = fmaxf(tx1, pr.x);
            float ly = fmaxf(ty1, pr.y);
            float rx = fminf(tx2, pr.z);
            float ry = fminf(ty2, pr.w);
            float wd = fmaxf(rx - lx, 0.0f);
            float ht = fmaxf(ry - ly, 0.0f);
            float inter = __fmul_rn(wd, ht);
            float denom = (tar + area_p) - inter;

            // Per-lane gate vs warp's current 4th (strict >, cross-mult).
            bool pass = __fmul_rn(inter, Ld3) > __fmul_rn(Li3, denom);
            unsigned m = __ballot_sync(0xffffffffu, pass);
            while (m) {                          // uniform loop (rare, ~7%)
                int l = __ffs(m) - 1; m &= m - 1;
                float ci = __shfl_sync(0xffffffffu, inter, l);
                float cd = __shfl_sync(0xffffffffu, denom, l);
                int   cx = base + i * 32 + l;    // global prior index (uniform)
                // Re-check vs (possibly updated) list — uniform branch.
                bool c3 = __fmul_rn(ci, Ld3) > __fmul_rn(Li3, cd);
                if (c3) {
                    bool c2 = __fmul_rn(ci, Ld2) > __fmul_rn(Li2, cd);
                    bool c1 = __fmul_rn(ci, Ld1) > __fmul_rn(Li1, cd);
                    bool c0 = __fmul_rn(ci, Ld0) > __fmul_rn(Li0, cd);
                    Li3 = c2 ? Li2 : ci;  Ld3 = c2 ? Ld2 : cd;  Lx3 = c2 ? Lx2 : cx;
                    Li2 = c1 ? Li1 : (c2 ? ci : Li2);
                    Ld2 = c1 ? Ld1 : (c2 ? cd : Ld2);
                    Lx2 = c1 ? Lx1 : (c2 ? cx : Lx2);
                    Li1 = c0 ? Li0 : (c1 ? ci : Li1);
                    Ld1 = c0 ? Ld0 : (c1 ? cd : Ld1);
                    Lx1 = c0 ? Lx0 : (c1 ? cx : Lx1);
                    Li0 = c0 ? ci : Li0;
                    Ld0 = c0 ? cd : Ld0;
                    Lx0 = c0 ? cx : Lx0;
                }
            }
        }
        __syncthreads();
    }

    // Epilogue: lanes 0..3 each finalize one survivor (exact jax-bit IoU).
    if (lane < TK) {
        float si = (lane == 0) ? Li0 : (lane == 1) ? Li1 : (lane == 2) ? Li2 : Li3;
        float sd = (lane == 0) ? Ld0 : (lane == 1) ? Ld1 : (lane == 2) ? Ld2 : Ld3;
        int   sx = (lane == 0) ? Lx0 : (lane == 1) ? Lx1 : (lane == 2) ? Lx2 : Lx3;
        float q = (sx == 0x7fffffff) ? -1e30f : __fdiv_rn(si, sd);
        g_cand[(size_t)(b * NG + g) * NCPT + cs * TK + lane] =
            make_float2(q, __int_as_float(sx));
    }

    // ── Last-block merge + encode (replaces phase 2) ────────────────────────
    __threadfence();
    __syncthreads();
    if (tid == 0) {
        int old = atomicAdd(&g_cnt[b * NTGRP + tg], 1);
        s_last = (old == CSPLIT - 1) ? 1 : 0;
    }
    __syncthreads();
    if (s_last) {
        __threadfence();
        if (tid < TPB * TK) {                       // 64 threads: (truth, k)
            int lt = tid >> 2, k = tid & 3;
            int bg = b * NG + tg * TPB + lt;

            float v[TK]; int ix[TK];
#pragma unroll
            for (int j = 0; j < TK; j++) { v[j] = -1e30f; ix[j] = 0x7fffffff; }

            const float4* cand = (const float4*)(g_cand + (size_t)bg * NCPT);
#pragma unroll
            for (int c = 0; c < NCPT / 2; c++) {
                float4 cc = __ldcg(&cand[c]);       // L2 (cross-SM data)
                float qs[2]  = {cc.x, cc.z};
                int   qis[2] = {__float_as_int(cc.y), __float_as_int(cc.w)};
#pragma unroll
                for (int t = 0; t < 2; t++) {
                    float q = qs[t]; int qi = qis[t];
                    if (better(q, qi, v[3], ix[3])) {
                        if (better(q, qi, v[2], ix[2])) {
                            v[3] = v[2]; ix[3] = ix[2];
                            if (better(q, qi, v[1], ix[1])) {
                                v[2] = v[1]; ix[2] = ix[1];
                                if (better(q, qi, v[0], ix[0])) {
                                    v[1] = v[0]; ix[1] = ix[0];
                                    v[0] = q; ix[0] = qi;
                                } else { v[1] = q; ix[1] = qi; }
                            } else { v[2] = q; ix[2] = qi; }
                        } else { v[3] = q; ix[3] = qi; }
                    }
                }
            }
            const int p = ix[k];

            // Encode one output row (identical rounding to reference).
            float gx1 = targets[(size_t)bg * 4 + 0];
            float gy1 = targets[(size_t)bg * 4 + 1];
            float gx2 = targets[(size_t)bg * 4 + 2];
            float gy2 = targets[(size_t)bg * 4 + 3];
            float gcx = (gx1 + gx2) * 0.5f;
            float gcy = (gy1 + gy2) * 0.5f;
            float gw  = gx2 - gx1;
            float gh  = gy2 - gy1;

            float4 pr = __ldg(&pri[p]);
            float pcx = (pr.x + pr.z) * 0.5f;
            float pcy = (pr.y + pr.w) * 0.5f;
            float pw  = pr.z - pr.x;
            float ph  = pr.w - pr.y;
            float4 o;
            o.x = (gcx - pcx) / (0.1f * pw);
            o.y = (gcy - pcy) / (0.1f * ph);
            o.z = logf(gw / pw) / 0.2f;
            o.w = logf(gh / ph) / 0.2f;
            ((float4*)out)[(size_t)bg * TK + k] = o;
        }
        if (tid == 0) g_cnt[b * NTGRP + tg] = 0;    // reset for next launch/replay
    }
}

extern "C" void kernel_launch(void* const* d_in, const int* in_sizes, int n_in,
                              void* d_out, int out_size) {
    const float* rois    = (const float*)d_in[0];   // (16, 2, 32768, 4) f32
    const float* targets = (const float*)d_in[1];   // (16, 128, 4) f32
    float* out           = (float*)d_out;           // (16, 512, 4) f32
    (void)in_sizes; (void)n_in; (void)out_size;

    ptl_fused<<<NB * NTGRP * CSPLIT, NT1>>>(rois, targets, out);
}

// round 14
// speedup vs baseline: 1.0525x; 1.0018x over previous
#include <cuda_runtime.h>
#include <math.h>

// Problem constants (fixed by setup_inputs)
#define NB 16
#define NP 32768
#define NG 128
#define TK 4                      // top-k (expand_num)
#define CSPLIT 4                  // prior-chunks per image (streams per truth)
#define WPB 8                     // warps (=truths) per block
#define NT1 (WPB * 32)            // 256 threads
#define TPB WPB                   // truths per block
#define NTGRP (NG / TPB)          // 16 truth-groups per image
#define CHUNK (NP / CSPLIT)       // 8192 priors per stream
#define TILE 2048                 // smem tile of priors
#define NTILES (CHUNK / TILE)     // 4
#define ITERS (TILE / 32)         // 64 warp-iters per tile
#define NBG (NB * NG)             // 2048 truths
#define NCPT (CSPLIT * TK)        // 16 candidates per truth

// Candidate buffer (256 KB) + last-block counters (zero-init, reset each launch).
__device__ float2 g_cand[NBG * NCPT];
__device__ int    g_cnt[NB * NTGRP];

// ── (q, idx) total order: value desc, index asc (jax.lax.top_k stable) ──────
__device__ __forceinline__ bool better(float av, int ai, float bv, int bi) {
    return (av > bv) || (av == bv && ai < bi);
}

// ── Fused kernel: warp = one truth; last block per (b,tg) merges + encodes ──
__global__ __launch_bounds__(NT1)
void ptl_fused(const float* __restrict__ rois,
               const float* __restrict__ targets,
               float* __restrict__ out) {
    const int blk  = blockIdx.x;                   // NB * NTGRP * CSPLIT = 1024
    const int b    = blk / (NTGRP * CSPLIT);
    const int rem  = blk % (NTGRP * CSPLIT);
    const int tg   = rem / CSPLIT;
    const int cs   = rem % CSPLIT;
    const int tid  = threadIdx.x;
    const int lane = tid & 31;
    const int w    = tid >> 5;
    const int g    = tg * TPB + w;                 // this warp's truth

    __shared__ float4 s_pri[TILE];                 // 32 KB
    __shared__ float  s_area[TILE];                // 8 KB
    __shared__ int    s_last;

    // My warp's truth box (uniform across lanes; L1-broadcast).
    float4 tb = __ldg(&((const float4*)targets)[(size_t)b * NG + g]);
    const float tx1 = tb.x, ty1 = tb.y, tx2 = tb.z, ty2 = tb.w;
    const float tar = __fmul_rn(tx2 - tx1, ty2 - ty1);    // rounded once (jax)

    // Warp-replicated top-4 as (inter, denom, idx); sentinel ratio = -1/1.
    float Li0 = -1.0f, Li1 = -1.0f, Li2 = -1.0f, Li3 = -1.0f;
    float Ld0 =  1.0f, Ld1 =  1.0f, Ld2 =  1.0f, Ld3 =  1.0f;
    int   Lx0 = 0x7fffffff, Lx1 = 0x7fffffff, Lx2 = 0x7fffffff, Lx3 = 0x7fffffff;
    // Conservative scalar threshold: T_lo <= exact 4th-place ratio (rd div).
    float T_lo = -1.0f;

    const float4* pri = (const float4*)(rois + ((size_t)b * 2 + 1) * (size_t)NP * 4);

    for (int tile = 0; tile < NTILES; tile++) {
        const int base = cs * CHUNK + tile * TILE;

        // Cooperative stage: 256 threads x 8 priors each (+ area precompute).
#pragma unroll
        for (int k = tid; k < TILE; k += NT1) {
            float4 pr = __ldg(&pri[base + k]);
            s_pri[k]  = pr;
            s_area[k] = __fmul_rn(pr.z - pr.x, pr.w - pr.y);  // jax bits
        }
        __syncthreads();

#pragma unroll 4
        for (int i = 0; i < ITERS; i++) {
            const int j = i * 32 + lane;
            float4 pr    = s_pri[j];              // LDS.128, conflict-free
            float area_p = s_area[j];             // LDS.32, conflict-free
            float lx = fmaxf(tx1, pr.x);
            float ly = fmaxf(ty1, pr.y);
            float rx = fminf(tx2, pr.z);
            float ry = fminf(ty2, pr.w);
            float wd = fmaxf(rx - lx, 0.0f);
            float ht = fmaxf(ry - ly, 0.0f);
            float inter = __fmul_rn(wd, ht);
            float denom = (tar + area_p) - inter;

            // 1-mul conservative gate: rd(T_lo*denom) <= exact r4*denom, so
            // any candidate strictly beating 4th place always passes.
            bool pass = inter > __fmul_rd(T_lo, denom);
            unsigned m = __ballot_sync(0xffffffffu, pass);
            if (m) {                              // uniform branch (rare)
                do {
                    int l = __ffs(m) - 1; m &= m - 1;
                    float ci = __shfl_sync(0xffffffffu, inter, l);
                    float cd = __shfl_sync(0xffffffffu, denom, l);
                    int   cx = base + i * 32 + l; // global prior index (uniform)
                    // Exact cross-mult re-check vs (possibly updated) list.
                    bool c3 = __fmul_rn(ci, Ld3) > __fmul_rn(Li3, cd);
                    if (c3) {
                        bool c2 = __fmul_rn(ci, Ld2) > __fmul_rn(Li2, cd);
                        bool c1 = __fmul_rn(ci, Ld1) > __fmul_rn(Li1, cd);
                        bool c0 = __fmul_rn(ci, Ld0) > __fmul_rn(Li0, cd);
                        Li3 = c2 ? Li2 : ci;  Ld3 = c2 ? Ld2 : cd;  Lx3 = c2 ? Lx2 : cx;
                        Li2 = c1 ? Li1 : (c2 ? ci : Li2);
                        Ld2 = c1 ? Ld1 : (c2 ? cd : Ld2);
                        Lx2 = c1 ? Lx1 : (c2 ? cx : Lx2);
                        Li1 = c0 ? Li0 : (c1 ? ci : Li1);
                        Ld1 = c0 ? Ld0 : (c1 ? cd : Ld1);
                        Lx1 = c0 ? Lx0 : (c1 ? cx : Lx1);
                        Li0 = c0 ? ci : Li0;
                        Ld0 = c0 ? cd : Ld0;
                        Lx0 = c0 ? cx : Lx0;
                    }
                } while (m);
                // Refresh threshold once per event (uniform; rd keeps it safe).
                T_lo = __fdiv_rd(Li3, Ld3);
            }
        }
        __syncthreads();
    }

    // Epilogue: lanes 0..3 each finalize one survivor (exact jax-bit IoU).
    if (lane < TK) {
        float si = (lane == 0) ? Li0 : (lane == 1) ? Li1 : (lane == 2) ? Li2 : Li3;
        float sd = (lane == 0) ? Ld0 : (lane == 1) ? Ld1 : (lane == 2) ? Ld2 : Ld3;
        int   sx = (lane == 0) ? Lx0 : (lane == 1) ? Lx1 : (lane == 2) ? Lx2 : Lx3;
        float q = (sx == 0x7fffffff) ? -1e30f : __fdiv_rn(si, sd);
        g_cand[(size_t)(b * NG + g) * NCPT + cs * TK + lane] =
            make_float2(q, __int_as_float(sx));
    }

    // ── Last-block merge + encode (replaces phase 2) ────────────────────────
    __threadfence();
    __syncthreads();
    if (tid == 0) {
        int old = atomicAdd(&g_cnt[b * NTGRP + tg], 1);
        s_last = (old == CSPLIT - 1) ? 1 : 0;
    }
    __syncthreads();
    if (s_last) {
        __threadfence();
        if (tid < TPB * TK) {                       // 32 threads: (truth, k)
            int lt = tid >> 2, k = tid & 3;
            int bg = b * NG + tg * TPB + lt;

            float v[TK]; int ix[TK];
#pragma unroll
            for (int j = 0; j < TK; j++) { v[j] = -1e30f; ix[j] = 0x7fffffff; }

            const float4* cand = (const float4*)(g_cand + (size_t)bg * NCPT);
#pragma unroll
            for (int c = 0; c < NCPT / 2; c++) {
                float4 cc = __ldcg(&cand[c]);       // L2 (cross-SM data)
                float qs[2]  = {cc.x, cc.z};
                int   qis[2] = {__float_as_int(cc.y), __float_as_int(cc.w)};
#pragma unroll
                for (int t = 0; t < 2; t++) {
                    float q = qs[t]; int qi = qis[t];
                    if (better(q, qi, v[3], ix[3])) {
                        if (better(q, qi, v[2], ix[2])) {
                            v[3] = v[2]; ix[3] = ix[2];
                            if (better(q, qi, v[1], ix[1])) {
                                v[2] = v[1]; ix[2] = ix[1];
                                if (better(q, qi, v[0], ix[0])) {
                                    v[1] = v[0]; ix[1] = ix[0];
                                    v[0] = q; ix[0] = qi;
                                } else { v[1] = q; ix[1] = qi; }
                            } else { v[2] = q; ix[2] = qi; }
                        } else { v[3] = q; ix[3] = qi; }
                    }
                }
            }
            const int p = ix[k];

            // Encode one output row (identical rounding to reference).
            float gx1 = targets[(size_t)bg * 4 + 0];
            float gy1 = targets[(size_t)bg * 4 + 1];
            float gx2 = targets[(size_t)bg * 4 + 2];
            float gy2 = targets[(size_t)bg * 4 + 3];
            float gcx = (gx1 + gx2) * 0.5f;
            float gcy = (gy1 + gy2) * 0.5f;
            float gw  = gx2 - gx1;
            float gh  = gy2 - gy1;

            float4 pr = __ldg(&pri[p]);
            float pcx = (pr.x + pr.z) * 0.5f;
            float pcy = (pr.y + pr.w) * 0.5f;
            float pw  = pr.z - pr.x;
            float ph  = pr.w - pr.y;
            float4 o;
            o.x = (gcx - pcx) / (0.1f * pw);
            o.y = (gcy - pcy) / (0.1f * ph);
            o.z = logf(gw / pw) / 0.2f;
            o.w = logf(gh / ph) / 0.2f;
            ((float4*)out)[(size_t)bg * TK + k] = o;
        }
        if (tid == 0) g_cnt[b * NTGRP + tg] = 0;    // reset for next launch/replay
    }
}

extern "C" void kernel_launch(void* const* d_in, const int* in_sizes, int n_in,
                              void* d_out, int out_size) {
    const float* rois    = (const float*)d_in[0];   // (16, 2, 32768, 4) f32
    const float* targets = (const float*)d_in[1];   // (16, 128, 4) f32
    float* out           = (float*)d_out;           // (16, 512, 4) f32
    (void)in_sizes; (void)n_in; (void)out_size;

    ptl_fused<<<NB * NTGRP * CSPLIT, NT1>>>(rois, targets, out);
}